// round 13
// baseline (speedup 1.0000x reference)
#include <cuda_runtime.h>
#include <stdint.h>

#define BOX 120
#define BOX3 1728000              // 120^3
#define MAXA 512
#define BT_C 44                   // BATCH(4) * NUM_TYPES(11)
#define THREADS 512
#define PLANE (BOX * BOX)         // 14400 floats
#define PLANE_F4 (PLANE / 4)      // 3600
#define PLANE_BYTES (PLANE * 4)   // 57600
#define RCAP 128                  // atoms per plane (mean ~21)

extern __shared__ float s_plane[];      // 57.6 KB dynamic

// Block = (bt, gx) full plane, SMEM accumulator with BULK-ASYNC epilogue:
//   A) issue coords LDG (1 atom/thread), zero smem plane under the loads,
//      append in-window atoms
//   B) scatter atoms into smem (shared atomics, ~21 atoms x <=25 cells)
//   C) ONE cp.async.bulk (TMA/UBLKCP) ships the whole plane smem->gmem:
//      no per-thread STG issue at all; wait only for the smem READ.
__global__ void __launch_bounds__(THREADS)
plane_tma_kernel(const float* __restrict__ coords,
                 const void* __restrict__ natoms_raw,
                 float* __restrict__ out) {
    __shared__ float4 s_rec[RCAP];      // {ay, az, wx, pack(cy,cz)}
    __shared__ int    s_cnt;

    const int b   = blockIdx.x;
    const int bt  = b / BOX;
    const int gx  = b - bt * BOX;
    const int tid = threadIdx.x;

    if (tid == 0) s_cnt = 0;

    // num_atoms may be int64 or int32 (jax x64 flag). Probe element 0: an
    // int32-packed buffer viewed as int64 carries n[1]>=1 in its high word,
    // far outside [1, MAXA].
    const long long* n64 = (const long long*)natoms_raw;
    const int*       n32 = (const int*)natoms_raw;
    long long probe = n64[0];
    int n = (probe >= 1 && probe <= MAXA) ? (int)n64[bt] : n32[bt];

    // ---- Phase A: coords loads in flight, zero plane, append records ----
    const float* cbase = coords + (long long)bt * (3 * MAXA);
    float ax = 0.f, ay = 0.f, az = 0.f;
    bool have = (tid < n);
    if (have) {
        ax = cbase[3 * tid + 0];
        ay = cbase[3 * tid + 1];
        az = cbase[3 * tid + 2];
    }
    __syncthreads();                    // s_cnt ready

    float4* sp4 = (float4*)s_plane;
    float4 z4 = make_float4(0.f, 0.f, 0.f, 0.f);
    #pragma unroll 7
    for (int i = tid; i < PLANE_F4; i += THREADS)
        sp4[i] = z4;

    if (have) {
        int cx = (int)floorf(ax);
        if ((unsigned)(gx - cx + 2) <= 4u) {           // x cell-window
            int cy = (int)floorf(ay);
            int cz = (int)floorf(az);
            float dx = (float)gx - ax;
            float wx = __expf(-dx * dx);
            int slot = atomicAdd(&s_cnt, 1);
            if (slot < RCAP)
                s_rec[slot] = make_float4(ay, az, wx,
                                          __int_as_float((cy & 0xffff) | (cz << 16)));
        }
    }
    __syncthreads();

    // ---- Phase B: scatter records into smem plane ----
    int cnt = min(s_cnt, RCAP);
    for (int idx = tid; idx < cnt; idx += THREADS) {
        float4 r = s_rec[idx];
        int cyz = __float_as_int(r.w);
        int cy = (int)(short)(cyz & 0xffff);
        int cz = cyz >> 16;
        float wx = r.z;

        float ez[5];
        #pragma unroll
        for (int k = 0; k < 5; ++k) {
            float dz = (float)(cz + k - 2) - r.y;
            ez[k] = __expf(-dz * dz);
        }
        #pragma unroll
        for (int j = 0; j < 5; ++j) {
            int gy = cy + j - 2;
            if ((unsigned)gy >= BOX) continue;
            float dy = (float)gy - r.x;
            float wxy = wx * __expf(-dy * dy);
            float* row = s_plane + gy * BOX;
            #pragma unroll
            for (int k = 0; k < 5; ++k) {
                int gz = cz + k - 2;
                if ((unsigned)gz < BOX)
                    atomicAdd(row + gz, wxy * ez[k]);
            }
        }
    }
    __syncthreads();

    // ---- Phase C: bulk-async plane store (no warp store issue) ----
    if (tid == 0) {
        // order generic-proxy smem writes (STS/atomics) before async-proxy read
        asm volatile("fence.proxy.async.shared::cta;" ::: "memory");
        uint32_t saddr;
        asm("{ .reg .u64 t; cvta.to.shared.u64 t, %1; cvt.u32.u64 %0, t; }"
            : "=r"(saddr) : "l"(s_plane));
        float* gdst = out + (long long)bt * BOX3 + (long long)gx * PLANE;
        asm volatile(
            "cp.async.bulk.global.shared::cta.bulk_group [%0], [%1], %2;"
            :: "l"(gdst), "r"(saddr), "n"(PLANE_BYTES) : "memory");
        asm volatile("cp.async.bulk.commit_group;" ::: "memory");
        // wait for the smem READ only; the gmem write drains asynchronously
        asm volatile("cp.async.bulk.wait_group.read 0;" ::: "memory");
    }
    __syncthreads();   // keep smem alive until the bulk read is done
}

extern "C" void kernel_launch(void* const* d_in, const int* in_sizes, int n_in,
                              void* d_out, int out_size) {
    const float* coords = (const float*)d_in[0];
    const void*  natoms = d_in[1];
    float* out = (float*)d_out;

    static bool attr_set = false;
    if (!attr_set) {
        cudaFuncSetAttribute(plane_tma_kernel,
                             cudaFuncAttributeMaxDynamicSharedMemorySize,
                             PLANE_BYTES);
        attr_set = true;
    }
    plane_tma_kernel<<<BT_C * BOX, THREADS, PLANE_BYTES>>>(coords, natoms, out);
}

// round 14
// speedup vs baseline: 1.1242x; 1.1242x over previous
#include <cuda_runtime.h>
#include <stdint.h>

#define BOX 120
#define BOX3 1728000            // 120^3
#define PLANE (BOX * BOX)
#define MAXA 512
#define BT_C 44                 // BATCH(4) * NUM_TYPES(11)
#define THREADS 256
#define NWARP (THREADS / 32)
#define ROW_F4 30               // 120/4 float4 per row
#define RCAP 160                // atoms per plane-pair (union window, mean ~26)
#define RLCAP 16                // entries per row list (mean ~1.05)

// Block = (bt, gx-pair). Two adjacent planes share ez tables and row lists;
// only the x-weight differs. Per entry Phase B does the gather ONCE and
// applies it to both planes (4 extra FFMA), halving non-store issue work.
//   A) scan atoms once for the 6-wide union x-window; hoist wxA, wxB, ey, ez
//   B) warp per row: per entry clamp-index LDS + dual FFMA; two STG.128/lane
__global__ void __launch_bounds__(THREADS)
pair_kernel(const float* __restrict__ coords,
            const void* __restrict__ natoms_raw,
            float* __restrict__ out) {
    __shared__ float  s_ez[RCAP * 8];       // [0]=0, [1..5]=ez, [6]=0, [7]=pad
    __shared__ float4 s_ent[BOX * RLCAP];   // {pack(slot,cz), wxyA, wxyB, pad}
    __shared__ int    s_rowcnt[BOX];
    __shared__ int    s_cnt;

    const int b    = blockIdx.x;
    const int bt   = b / (BOX / 2);
    const int gxA  = (b - bt * (BOX / 2)) * 2;   // planes gxA, gxA+1
    const int tid  = threadIdx.x;
    const int wid  = tid >> 5;
    const int lane = tid & 31;

    if (tid < BOX) s_rowcnt[tid] = 0;
    if (tid == 0) s_cnt = 0;

    // num_atoms may be int64 or int32 (jax x64 flag). Probe element 0: an
    // int32-packed buffer viewed as int64 carries n[1]>=1 in its high word,
    // far outside [1, MAXA].
    const long long* n64 = (const long long*)natoms_raw;
    const int*       n32 = (const int*)natoms_raw;
    long long probe = n64[0];
    int n = (probe >= 1 && probe <= MAXA) ? (int)n64[bt] : n32[bt];
    __syncthreads();

    // ---- Phase A: one atom scan serves both planes ----
    const float* cbase = coords + (long long)bt * (3 * MAXA);
    for (int a = tid; a < n; a += THREADS) {
        float ax = cbase[3 * a + 0];
        int cx = (int)floorf(ax);
        // union window: cx in [gxA-2, gxA+3]
        if ((unsigned)(gxA - cx + 3) > 5u) continue;
        float ay = cbase[3 * a + 1];
        float az = cbase[3 * a + 2];
        int cy = (int)floorf(ay);
        int cz = (int)floorf(az);

        bool inA = (unsigned)(gxA - cx + 2) <= 4u;
        bool inB = (unsigned)(gxA + 1 - cx + 2) <= 4u;
        float dxA = (float)gxA - ax;
        float dxB = dxA + 1.f;
        float wxA = inA ? __expf(-dxA * dxA) : 0.f;
        float wxB = inB ? __expf(-dxB * dxB) : 0.f;

        int slot = atomicAdd(&s_cnt, 1);
        if (slot >= RCAP) continue;

        float* ezp = s_ez + slot * 8;
        ezp[0] = 0.f;
        #pragma unroll
        for (int k = 0; k < 5; ++k) {
            int gz = cz + k - 2;
            float dz = (float)gz - az;
            ezp[k + 1] = ((unsigned)gz < BOX) ? __expf(-dz * dz) : 0.f;
        }
        ezp[6] = 0.f;

        float fpk = __int_as_float((slot & 0xffff) | (cz << 16));
        int r0 = max(cy - 2, 0), r1 = min(cy + 2, BOX - 1);
        for (int r = r0; r <= r1; ++r) {
            float dy = (float)r - ay;
            float ey = __expf(-dy * dy);
            int rs = atomicAdd(&s_rowcnt[r], 1);
            if (rs < RLCAP)
                s_ent[r * RLCAP + rs] =
                    make_float4(fpk, wxA * ey, wxB * ey, 0.f);
        }
    }
    __syncthreads();

    // ---- Phase B: warp per row; shared gather feeds both planes ----
    float* obaseA = out + (long long)bt * BOX3 + (long long)gxA * PLANE;
    float* obaseB = obaseA + PLANE;
    for (int r = wid; r < BOX; r += NWARP) {
        int cnt = min(s_rowcnt[r], RLCAP);
        if (lane < ROW_F4) {
            float a0 = 0.f, a1 = 0.f, a2 = 0.f, a3 = 0.f;
            float b0 = 0.f, b1 = 0.f, b2 = 0.f, b3 = 0.f;
            int z0 = lane * 4;
            for (int j = 0; j < cnt; ++j) {
                float4 e = s_ent[r * RLCAP + j];
                int bits = __float_as_int(e.x);
                const float* ezp = s_ez + (bits & 0xffff) * 8;
                int base = z0 - (bits >> 16) + 3;    // in-window -> [1,5]
                float t0 = ezp[min(max(base + 0, 0), 6)];
                float t1 = ezp[min(max(base + 1, 0), 6)];
                float t2 = ezp[min(max(base + 2, 0), 6)];
                float t3 = ezp[min(max(base + 3, 0), 6)];
                a0 += e.y * t0; a1 += e.y * t1; a2 += e.y * t2; a3 += e.y * t3;
                b0 += e.z * t0; b1 += e.z * t1; b2 += e.z * t2; b3 += e.z * t3;
            }
            __stcs((float4*)(obaseA + r * BOX) + lane,
                   make_float4(a0, a1, a2, a3));
            __stcs((float4*)(obaseB + r * BOX) + lane,
                   make_float4(b0, b1, b2, b3));
        }
    }
}

extern "C" void kernel_launch(void* const* d_in, const int* in_sizes, int n_in,
                              void* d_out, int out_size) {
    const float* coords = (const float*)d_in[0];
    const void*  natoms = d_in[1];
    float* out = (float*)d_out;
    pair_kernel<<<BT_C * (BOX / 2), THREADS>>>(coords, natoms, out);
}

// round 16
// speedup vs baseline: 1.1620x; 1.0336x over previous
#include <cuda_runtime.h>
#include <stdint.h>

#define BOX 120
#define BOX3 1728000            // 120^3
#define PLANE (BOX * BOX)
#define PLANE_F4 (PLANE / 4)    // 3600
#define MAXA 512
#define BT_C 44                 // BATCH(4) * NUM_TYPES(11)
#define THREADS 256
#define ROW_F4 30               // 120/4 float4 per row
#define RCAP 128                // atom records per plane (mean ~21)
#define RLCAP 16                // entries per row list (mean ~0.9)

// Block = (bt, gx) full plane. R12 platform (all exp hoisted to Phase A,
// zero-padded ez tables, per-row entry lists) with a linear f4 store map:
// every lane stores, store address is obase4 + i, 6% fewer store iterations.
__global__ void __launch_bounds__(THREADS)
rowlist_kernel(const float* __restrict__ coords,
               const void* __restrict__ natoms_raw,
               float* __restrict__ out) {
    __shared__ float  s_ez[RCAP * 8];          // [0]=0, [1..5]=ez, [6]=0, [7]=pad
    __shared__ float2 s_ent[BOX * RLCAP];      // {pack(slot,cz), wxy}
    __shared__ int    s_rowcnt[BOX];
    __shared__ int    s_cnt;

    const int b   = blockIdx.x;
    const int bt  = b / BOX;
    const int gx  = b - bt * BOX;
    const int tid = threadIdx.x;

    if (tid < BOX) s_rowcnt[tid] = 0;
    if (tid == 0) s_cnt = 0;

    // num_atoms may be int64 or int32 (jax x64 flag). Probe element 0: an
    // int32-packed buffer viewed as int64 carries n[1]>=1 in its high word,
    // far outside [1, MAXA].
    const long long* n64 = (const long long*)natoms_raw;
    const int*       n32 = (const int*)natoms_raw;
    long long probe = n64[0];
    int n = (probe >= 1 && probe <= MAXA) ? (int)n64[bt] : n32[bt];
    __syncthreads();

    // ---- Phase A: collect atoms; hoist ALL exponentials here ----
    const float* cbase = coords + (long long)bt * (3 * MAXA);
    for (int a = tid; a < n; a += THREADS) {
        float ax = cbase[3 * a + 0];
        int cx = (int)floorf(ax);
        if ((unsigned)(gx - cx + 2) > 4u) continue;      // x cell-window
        float ay = cbase[3 * a + 1];
        float az = cbase[3 * a + 2];
        int cy = (int)floorf(ay);
        int cz = (int)floorf(az);
        float dx = (float)gx - ax;
        float wx = __expf(-dx * dx);

        int slot = atomicAdd(&s_cnt, 1);
        if (slot >= RCAP) continue;

        float* ezp = s_ez + slot * 8;                    // zero-padded guards
        ezp[0] = 0.f;
        #pragma unroll
        for (int k = 0; k < 5; ++k) {
            int gz = cz + k - 2;
            float dz = (float)gz - az;
            ezp[k + 1] = ((unsigned)gz < BOX) ? __expf(-dz * dz) : 0.f;
        }
        ezp[6] = 0.f;

        int packed = (slot & 0xffff) | (cz << 16);
        int r0 = max(cy - 2, 0), r1 = min(cy + 2, BOX - 1);
        for (int r = r0; r <= r1; ++r) {
            float dy = (float)r - ay;
            float wxy = wx * __expf(-dy * dy);
            int rs = atomicAdd(&s_rowcnt[r], 1);
            if (rs < RLCAP)
                s_ent[r * RLCAP + rs] =
                    make_float2(__int_as_float(packed), wxy);
        }
    }
    __syncthreads();

    // ---- Phase B: linear f4 map over the contiguous plane ----
    float4* obase4 = (float4*)(out + (long long)bt * BOX3
                                   + (long long)gx * PLANE);
    for (int i = tid; i < PLANE_F4; i += THREADS) {
        int r  = i / ROW_F4;                 // row (mul-shift)
        int z0 = (i - r * ROW_F4) * 4;
        int cnt = min(s_rowcnt[r], RLCAP);
        float v0 = 0.f, v1 = 0.f, v2 = 0.f, v3 = 0.f;
        for (int j = 0; j < cnt; ++j) {
            float2 e = s_ent[r * RLCAP + j];
            int bits = __float_as_int(e.x);
            const float* ezp = s_ez + (bits & 0xffff) * 8;
            float wxy = e.y;
            int base = z0 - (bits >> 16) + 3;   // in-window -> [1,5]
            v0 += wxy * ezp[min(max(base + 0, 0), 6)];
            v1 += wxy * ezp[min(max(base + 1, 0), 6)];
            v2 += wxy * ezp[min(max(base + 2, 0), 6)];
            v3 += wxy * ezp[min(max(base + 3, 0), 6)];
        }
        __stcs(obase4 + i, make_float4(v0, v1, v2, v3));
    }
}

extern "C" void kernel_launch(void* const* d_in, const int* in_sizes, int n_in,
                              void* d_out, int out_size) {
    const float* coords = (const float*)d_in[0];
    const void*  natoms = d_in[1];
    float* out = (float*)d_out;
    rowlist_kernel<<<BT_C * BOX, THREADS>>>(coords, natoms, out);
}